// round 8
// baseline (speedup 1.0000x reference)
#include <cuda_runtime.h>
#include <math.h>

#define ATOMS 48
#define CAP   48          // per-species bucket capacity (worst case)
#define BLK   128

// cos/sin of SHF_Z[z] = (2z+1)*pi/16
__device__ __constant__ float COSZ[8] = {
     0.98078528040323044913f,  0.83146961230254523708f,
     0.55557023301960222474f,  0.19509032201612826785f,
    -0.19509032201612826785f, -0.55557023301960222474f,
    -0.83146961230254523708f, -0.98078528040323044913f };
__device__ __constant__ float SINZ[8] = {
     0.19509032201612826785f,  0.55557023301960222474f,
     0.83146961230254523708f,  0.98078528040323044913f,
     0.98078528040323044913f,  0.83146961230254523708f,
     0.55557023301960222474f,  0.19509032201612826785f };

// PAIR_IDX for 4 species (upper-triangular enumeration, symmetric)
__device__ __constant__ int PAIRT[4][4] = {
    {0,1,2,3},{1,4,5,6},{2,5,7,8},{3,6,8,9} };

__global__ void __launch_bounds__(BLK, 8)
aev_kernel(const int* __restrict__ species, const float* __restrict__ coords,
           float* __restrict__ aev_out, float* __restrict__ sp_out)
{
    const int i = blockIdx.x;          // atom within batch
    const int b = blockIdx.y;          // batch
    const int A = gridDim.x;           // 48
    const int tid = threadIdx.x;

    __shared__ float cx[ATOMS], cy[ATOMS], cz[ATOMS];
    __shared__ int   sp[ATOMS];
    __shared__ float4 bvec[4*CAP];     // (vx, vy, vz, d) angular buckets
    __shared__ float2 bsc[4*CAP];      // (1/d, fc_a)
    __shared__ float2 rpak[4*CAP];     // (d, 0.25*fc_r) radial buckets
    __shared__ int   cnt[4], rcnt[4];
    __shared__ int   jlist[CAP];       // packed: slot | (s_j << 8)
    __shared__ int   Mtot;
    __shared__ float ang4[4][320];     // 4-way sliced angular accumulator

    const float* cb = coords + (size_t)b * A * 3;
    if (tid < A) {
        cx[tid] = cb[tid*3 + 0];
        cy[tid] = cb[tid*3 + 1];
        cz[tid] = cb[tid*3 + 2];
        sp[tid] = species[b*A + tid];
    }
    if (tid < 4)  { cnt[tid] = 0; rcnt[tid] = 0; }
    if (tid == 4) Mtot = 0;
    for (int t = tid; t < 4*320; t += BLK) ((float*)ang4)[t] = 0.0f;
    __syncthreads();

    const float xi = cx[i], yi = cy[i], zi = cz[i];

    // ---- phase 1: distances, bucketed neighbor lists ----
    if (tid < A && tid != i) {
        float dx = cx[tid] - xi;
        float dy = cy[tid] - yi;
        float dz = cz[tid] - zi;
        float d  = sqrtf(dx*dx + dy*dy + dz*dz);
        int   s  = sp[tid];
        if (d <= 5.2f) {
            float fcr = 0.5f * cospif(d / 5.2f) + 0.5f;
            int m = atomicAdd(&rcnt[s], 1);
            rpak[s*CAP + m] = make_float2(d, 0.25f * fcr);
        }
        if (d <= 3.5f) {
            float fca = 0.5f * cospif(d / 3.5f) + 0.5f;
            int m    = atomicAdd(&cnt[s], 1);
            int slot = s*CAP + m;
            bvec[slot] = make_float4(dx, dy, dz, d);
            bsc[slot]  = make_float2(1.0f / d, fca);
            int pos = atomicAdd(&Mtot, 1);
            jlist[pos] = slot | (s << 8);
        }
    }
    __syncthreads();

    // ---- phase 2: workers (sk, split, j); k strided by 2 per split ----
    // sk-major so warp lanes share the species bucket; split halves the
    // inner trip count. Ordered-pair sum with weight fc_j*fc_k equals the
    // reference's unordered sum with weight 2*fc_j*fc_k (symmetric j,k).
    const float K1 = __expf(-6.76f);   // exp step for the f2 recurrence
    const int M = Mtot;
    const int W = 8 * M;               // 4 species * 2 splits * M groups
    for (int w = tid; w < W; w += BLK) {
        const int sk   = w / (2*M);
        int rem        = w - sk*2*M;
        const int s    = (rem >= M) ? 1 : 0;
        const int jidx = rem - s*M;
        const int jid   = jlist[jidx];
        const int jslot = jid & 255;
        const int sj    = jid >> 8;

        const float4 jv = bvec[jslot];
        const float2 js = bsc[jslot];

        float acc[32];
        #pragma unroll
        for (int q = 0; q < 32; q++) acc[q] = 0.0f;

        const int n    = cnt[sk];
        const int base = sk * CAP;
        for (int m = s; m < n; m += 2) {
            const int kslot = base + m;
            float4 kv = bvec[kslot];
            float2 ks = bsc[kslot];
            float dot = jv.x*kv.x + jv.y*kv.y + jv.z*kv.z;
            float ct  = 0.95f * dot * js.x * ks.x;        // |ct| <= 0.95
            float st  = sqrtf(fmaxf(1.0f - ct*ct, 0.0f));
            float avg = 0.5f * (jv.w + kv.w);
            float wgt = (kslot == jslot) ? 0.0f : js.y * ks.y;

            // f2v[a] = w*exp(-8*(u-0.65a)^2) via exact geometric recurrence
            float u   = avg - 0.9f;
            float f0  = wgt * __expf(-8.0f * u * u);
            float r   = __expf(fmaf(10.4f, u, -3.38f));
            float f1v = f0 * r;
            float r2  = r * K1;
            float f2v = f1v * r2;
            float r3  = r2 * K1;
            float f3v = f2v * r3;

            #pragma unroll
            for (int z = 0; z < 8; z++) {
                float c   = ct * COSZ[z] + st * SINZ[z];  // cos(acos(ct)-shfz)
                float b1  = 0.5f + 0.5f * c;
                float b2  = b1 * b1;
                float b4  = b2 * b2;
                float b8  = b4 * b4;
                float b16 = b8 * b8;
                float f1  = b16 * b16;                    // b1^32
                acc[0*8 + z] += f0  * f1;
                acc[1*8 + z] += f1v * f1;
                acc[2*8 + z] += f2v * f1;
                acc[3*8 + z] += f3v * f1;
            }
        }

        float* angp = &ang4[tid & 3][PAIRT[sj][sk] * 32];
        #pragma unroll
        for (int q = 0; q < 32; q++) atomicAdd(&angp[q], acc[q]);
    }
    __syncthreads();

    // ---- phase 3: radial features + output ----
    float* o = aev_out + (size_t)(b * A + i) * 384;

    // radial: feature (s, r); 16-lane groups share species s
    if (tid < 64) {
        const int s = tid >> 4;
        const int r = tid & 15;
        const float shf = 0.9f + 0.26875f * (float)r;
        const int n = rcnt[s];
        float acc = 0.0f;
        for (int m = 0; m < n; m++) {
            float2 v = rpak[s*CAP + m];    // broadcast within 16-lane group
            float u = v.x - shf;
            acc += v.y * __expf(-16.0f * u * u);
        }
        o[tid] = acc;
    }

    // angular: reduce 4 slices, direct write
    #pragma unroll
    for (int base = 0; base < 384; base += BLK) {
        int f = base + tid;
        if (f < 320)
            o[64 + f] = ang4[0][f] + ang4[1][f] + ang4[2][f] + ang4[3][f];
    }

    if (sp_out != nullptr && tid == 0)
        sp_out[b * A + i] = (float)sp[i];
}

extern "C" void kernel_launch(void* const* d_in, const int* in_sizes, int n_in,
                              void* d_out, int out_size)
{
    const int*   species = (const int*)d_in[0];
    const float* coords  = (const float*)d_in[1];

    const int BA = in_sizes[0];     // B*A
    const int A  = ATOMS;           // 48 per reference
    const int B  = BA / A;
    const int aev_total = BA * 384;

    float* out    = (float*)d_out;
    float* sp_out = nullptr;
    float* aev    = out;
    if (out_size >= aev_total + BA) {   // tuple output: species first, then aevs
        sp_out = out;
        aev    = out + BA;
    }

    dim3 grid(A, B);
    aev_kernel<<<grid, BLK>>>(species, coords, aev, sp_out);
}

// round 9
// speedup vs baseline: 2.4225x; 2.4225x over previous
#include <cuda_runtime.h>
#include <math.h>

#define ATOMS 48
#define CAP   48          // per-species bucket capacity (worst case)
#define BLK   128

// cos/sin of SHF_Z[z] = (2z+1)*pi/16
__device__ __constant__ float COSZ[8] = {
     0.98078528040323044913f,  0.83146961230254523708f,
     0.55557023301960222474f,  0.19509032201612826785f,
    -0.19509032201612826785f, -0.55557023301960222474f,
    -0.83146961230254523708f, -0.98078528040323044913f };
__device__ __constant__ float SINZ[8] = {
     0.19509032201612826785f,  0.55557023301960222474f,
     0.83146961230254523708f,  0.98078528040323044913f,
     0.98078528040323044913f,  0.83146961230254523708f,
     0.55557023301960222474f,  0.19509032201612826785f };

// PAIR_IDX for 4 species (upper-triangular enumeration, symmetric)
__device__ __constant__ int PAIRT[4][4] = {
    {0,1,2,3},{1,4,5,6},{2,5,7,8},{3,6,8,9} };

__global__ void __launch_bounds__(BLK, 8)
aev_kernel(const int* __restrict__ species, const float* __restrict__ coords,
           float* __restrict__ aev_out, float* __restrict__ sp_out)
{
    const int i = blockIdx.x;          // atom within batch
    const int b = blockIdx.y;          // batch
    const int A = gridDim.x;           // 48
    const int tid = threadIdx.x;

    __shared__ float cx[ATOMS], cy[ATOMS], cz[ATOMS];
    __shared__ int   sp[ATOMS];
    __shared__ float4 bvec[4*CAP];     // (vx, vy, vz, d) angular buckets
    __shared__ float2 bsc[4*CAP];      // (1/d, fc_a)
    __shared__ float2 rpak[4*CAP];     // (d, 0.25*fc_r) radial buckets
    __shared__ int   cnt[4], rcnt[4];
    __shared__ int   jlist[CAP];       // packed: slot | (s_j << 8)
    __shared__ int   Mtot;
    __shared__ float ang4[4][320];     // 4-way sliced angular accumulator

    const float* cb = coords + (size_t)b * A * 3;
    if (tid < A) {
        cx[tid] = cb[tid*3 + 0];
        cy[tid] = cb[tid*3 + 1];
        cz[tid] = cb[tid*3 + 2];
        sp[tid] = species[b*A + tid];
    }
    if (tid < 4)  { cnt[tid] = 0; rcnt[tid] = 0; }
    if (tid == 4) Mtot = 0;
    for (int t = tid; t < 4*320; t += BLK) ((float*)ang4)[t] = 0.0f;
    __syncthreads();

    const float xi = cx[i], yi = cy[i], zi = cz[i];

    // ---- phase 1: distances, bucketed neighbor lists ----
    if (tid < A && tid != i) {
        float dx = cx[tid] - xi;
        float dy = cy[tid] - yi;
        float dz = cz[tid] - zi;
        float d  = sqrtf(dx*dx + dy*dy + dz*dz);
        int   s  = sp[tid];
        if (d <= 5.2f) {
            float fcr = 0.5f * cospif(d / 5.2f) + 0.5f;
            int m = atomicAdd(&rcnt[s], 1);
            rpak[s*CAP + m] = make_float2(d, 0.25f * fcr);
        }
        if (d <= 3.5f) {
            float fca = 0.5f * cospif(d / 3.5f) + 0.5f;
            int m    = atomicAdd(&cnt[s], 1);
            int slot = s*CAP + m;
            bvec[slot] = make_float4(dx, dy, dz, d);
            bsc[slot]  = make_float2(1.0f / d, fca);
            int pos = atomicAdd(&Mtot, 1);
            jlist[pos] = slot | (s << 8);
        }
    }
    __syncthreads();

    // ---- phase 2: workers (sk, zhalf, j); 16 features each (4a x 4z) ----
    // sk-major + half-major: warp lanes share sk => same inner trip count.
    // Ordered-pair sum with weight fc_j*fc_k equals the reference's
    // unordered sum with weight 2*fc_j*fc_k (integrand symmetric in j,k).
    const float K1 = __expf(-6.76f);   // exp step for the f2 recurrence
    const int M = Mtot;
    const int M2 = 2 * M;
    const int W = 8 * M;               // 4 species * 2 z-halves * M groups
    for (int w = tid; w < W; w += BLK) {
        const int sk   = w / M2;
        int rem        = w - sk * M2;
        const int h    = (rem >= M) ? 1 : 0;   // z-half: z in [4h, 4h+4)
        const int jidx = rem - h * M;
        const int jid   = jlist[jidx];
        const int jslot = jid & 255;
        const int sj    = jid >> 8;
        const int zb    = 4 * h;

        const float4 jv = bvec[jslot];
        const float2 js = bsc[jslot];

        float acc[16];                 // [a][z'] z' = z - zb
        #pragma unroll
        for (int q = 0; q < 16; q++) acc[q] = 0.0f;

        const int n    = cnt[sk];
        const int base = sk * CAP;
        for (int m = 0; m < n; m++) {
            const int kslot = base + m;
            float4 kv = bvec[kslot];
            float2 ks = bsc[kslot];
            float dot = jv.x*kv.x + jv.y*kv.y + jv.z*kv.z;
            float ct  = 0.95f * dot * js.x * ks.x;        // |ct| <= 0.95
            float st  = sqrtf(fmaxf(1.0f - ct*ct, 0.0f));
            float avg = 0.5f * (jv.w + kv.w);
            float wgt = (kslot == jslot) ? 0.0f : js.y * ks.y;

            // f2v[a] = w*exp(-8*(u-0.65a)^2) via exact geometric recurrence
            float u   = avg - 0.9f;
            float f0  = wgt * __expf(-8.0f * u * u);
            float r   = __expf(fmaf(10.4f, u, -3.38f));
            float f1v = f0 * r;
            float r2  = r * K1;
            float f2v = f1v * r2;
            float r3  = r2 * K1;
            float f3v = f2v * r3;

            #pragma unroll
            for (int zq = 0; zq < 4; zq++) {
                float c   = ct * COSZ[zb + zq] + st * SINZ[zb + zq];
                float b1  = 0.5f + 0.5f * c;
                float b2  = b1 * b1;
                float b4  = b2 * b2;
                float b8  = b4 * b4;
                float b16 = b8 * b8;
                float f1  = b16 * b16;                    // ((1+c)/2)^32
                acc[0*4 + zq] += f0  * f1;
                acc[1*4 + zq] += f1v * f1;
                acc[2*4 + zq] += f2v * f1;
                acc[3*4 + zq] += f3v * f1;
            }
        }

        float* angp = &ang4[tid & 3][PAIRT[sj][sk] * 32 + zb];
        #pragma unroll
        for (int a = 0; a < 4; a++)
            #pragma unroll
            for (int zq = 0; zq < 4; zq++)
                atomicAdd(&angp[a*8 + zq], acc[a*4 + zq]);
    }
    __syncthreads();

    // ---- phase 3: radial features + output ----
    float* o = aev_out + (size_t)(b * A + i) * 384;

    // radial: feature (s, r); 16-lane groups share species s
    if (tid < 64) {
        const int s = tid >> 4;
        const int r = tid & 15;
        const float shf = 0.9f + 0.26875f * (float)r;
        const int n = rcnt[s];
        float acc = 0.0f;
        for (int m = 0; m < n; m++) {
            float2 v = rpak[s*CAP + m];    // broadcast within 16-lane group
            float u = v.x - shf;
            acc += v.y * __expf(-16.0f * u * u);
        }
        o[tid] = acc;
    }

    // angular: reduce 4 slices, direct write
    #pragma unroll
    for (int base = 0; base < 384; base += BLK) {
        int f = base + tid;
        if (f < 320)
            o[64 + f] = ang4[0][f] + ang4[1][f] + ang4[2][f] + ang4[3][f];
    }

    if (sp_out != nullptr && tid == 0)
        sp_out[b * A + i] = (float)sp[i];
}

extern "C" void kernel_launch(void* const* d_in, const int* in_sizes, int n_in,
                              void* d_out, int out_size)
{
    const int*   species = (const int*)d_in[0];
    const float* coords  = (const float*)d_in[1];

    const int BA = in_sizes[0];     // B*A
    const int A  = ATOMS;           // 48 per reference
    const int B  = BA / A;
    const int aev_total = BA * 384;

    float* out    = (float*)d_out;
    float* sp_out = nullptr;
    float* aev    = out;
    if (out_size >= aev_total + BA) {   // tuple output: species first, then aevs
        sp_out = out;
        aev    = out + BA;
    }

    dim3 grid(A, B);
    aev_kernel<<<grid, BLK>>>(species, coords, aev, sp_out);
}